// round 1
// baseline (speedup 1.0000x reference)
#include <cuda_runtime.h>
#include <math.h>
#include <math_constants.h>

#define DIM    256
#define NEMB   2048
#define NROWS  65536               // 16*64*64
#define QELEMS (NROWS * DIM)       // 16777216
#define GATHER_BLOCKS 16384        // 16384*256 threads * 4 floats = QELEMS

// ---- scratch (no allocations allowed) ----
__device__ float  g_embedT[NEMB * DIM];   // [2048][256] transposed codebook
__device__ float  g_sumE2[NEMB];
__device__ int    g_idx[NROWS];
__device__ int    g_counts[NEMB];
__device__ double g_partials[GATHER_BLOCKS];

// ============================================================
// Kernel 0: transpose embed, compute ||e_j||^2, zero histogram.
// Rerun every launch so graph replays are deterministic.
// ============================================================
__global__ void __launch_bounds__(256) prep_kernel(const float* __restrict__ embed) {
    int j = blockIdx.x * 256 + threadIdx.x;
    if (j < NEMB) {
        float s = 0.0f;
        #pragma unroll 8
        for (int d = 0; d < DIM; d++) {
            float v = embed[(size_t)d * NEMB + j];   // coalesced over j
            g_embedT[(size_t)j * DIM + d] = v;
            s = __fadd_rn(s, __fmul_rn(v, v));
        }
        g_sumE2[j]  = s;
        g_counts[j] = 0;
    }
}

// ============================================================
// Kernel 1: distance + argmin.
// Block: 64 rows. SMEM: Xs[256][64] (64KB) + Es[32][64] (8KB) + sx2[64].
// 256 threads as 16x16; each thread owns a 4x4 (row x code) micro-tile.
// ============================================================
#define SMEM_MAIN_BYTES ((16384 + 2048 + 64) * 4)   // 73984

__global__ void __launch_bounds__(256) dist_argmin_kernel(
    const float* __restrict__ input,
    const float* __restrict__ embed,
    float* __restrict__ indOutF)
{
    extern __shared__ float sm[];
    float* Xs   = sm;                 // [k=256][m=64]
    float* Es   = sm + 16384;         // [k=32][n=64]
    float* sx2s = sm + 16384 + 2048;  // [64]

    const int tid  = threadIdx.x;
    const int tx   = tid & 15;        // code group
    const int ty   = tid >> 4;        // row group
    const int row0 = blockIdx.x * 64;

    // --- load 64 rows of X into SMEM (k-major) ---
    const float4* inp4 = (const float4*)(input + (size_t)row0 * DIM);
    for (int i = tid; i < 4096; i += 256) {     // 64 rows * 64 float4
        int m = i >> 6, k4 = i & 63;
        float4 v = inp4[i];
        int k = k4 << 2;
        Xs[(k + 0) * 64 + m] = v.x;
        Xs[(k + 1) * 64 + m] = v.y;
        Xs[(k + 2) * 64 + m] = v.z;
        Xs[(k + 3) * 64 + m] = v.w;
    }
    __syncthreads();

    // --- ||x||^2 per row (sequential ascending k, product-then-add) ---
    if (tid < 64) {
        float s = 0.0f;
        for (int k = 0; k < DIM; k++) {
            float v = Xs[k * 64 + tid];
            s = __fadd_rn(s, __fmul_rn(v, v));
        }
        sx2s[tid] = s;
    }
    __syncthreads();

    float best[4];
    int   bidx[4];
    #pragma unroll
    for (int i = 0; i < 4; i++) { best[i] = CUDART_INF_F; bidx[i] = 0x7fffffff; }

    for (int j0 = 0; j0 < NEMB; j0 += 64) {
        float acc[4][4] = {};

        #pragma unroll 1
        for (int kc = 0; kc < 8; kc++) {
            // stage Es: 32 k x 64 n = 512 float4, 2 per thread
            #pragma unroll
            for (int it = 0; it < 2; it++) {
                int i  = tid + it * 256;
                int k  = i >> 4, n4 = i & 15;
                float4 v = *(const float4*)(embed + (size_t)(kc * 32 + k) * NEMB
                                            + j0 + (n4 << 2));
                *(float4*)(Es + k * 64 + (n4 << 2)) = v;
            }
            __syncthreads();

            #pragma unroll
            for (int k = 0; k < 32; k++) {
                float4 a = *(const float4*)(Xs + (kc * 32 + k) * 64 + (ty << 2));
                float4 b = *(const float4*)(Es + k * 64 + (tx << 2));
                acc[0][0] = fmaf(a.x, b.x, acc[0][0]);
                acc[0][1] = fmaf(a.x, b.y, acc[0][1]);
                acc[0][2] = fmaf(a.x, b.z, acc[0][2]);
                acc[0][3] = fmaf(a.x, b.w, acc[0][3]);
                acc[1][0] = fmaf(a.y, b.x, acc[1][0]);
                acc[1][1] = fmaf(a.y, b.y, acc[1][1]);
                acc[1][2] = fmaf(a.y, b.z, acc[1][2]);
                acc[1][3] = fmaf(a.y, b.w, acc[1][3]);
                acc[2][0] = fmaf(a.z, b.x, acc[2][0]);
                acc[2][1] = fmaf(a.z, b.y, acc[2][1]);
                acc[2][2] = fmaf(a.z, b.z, acc[2][2]);
                acc[2][3] = fmaf(a.z, b.w, acc[2][3]);
                acc[3][0] = fmaf(a.w, b.x, acc[3][0]);
                acc[3][1] = fmaf(a.w, b.y, acc[3][1]);
                acc[3][2] = fmaf(a.w, b.z, acc[3][2]);
                acc[3][3] = fmaf(a.w, b.w, acc[3][3]);
            }
            __syncthreads();
        }

        // epilogue: dist = sx2 - 2*dot + se2 (reference op order), running argmin
        float se2v[4];
        #pragma unroll
        for (int ni = 0; ni < 4; ni++)
            se2v[ni] = __ldg(&g_sumE2[j0 + (tx << 2) + ni]);

        #pragma unroll
        for (int mi = 0; mi < 4; mi++) {
            float sx2 = sx2s[(ty << 2) + mi];
            #pragma unroll
            for (int ni = 0; ni < 4; ni++) {
                float t = __fmul_rn(2.0f, acc[mi][ni]);   // exact
                float d = __fsub_rn(sx2, t);
                d = __fadd_rn(d, se2v[ni]);
                if (d < best[mi]) {                        // strict: first-min wins
                    best[mi] = d;
                    bidx[mi] = j0 + (tx << 2) + ni;
                }
            }
        }
    }
    __syncthreads();

    // cross-thread reduction per row (tie -> smaller index)
    float* redD = Es;                 // 1024 floats
    int*   redI = (int*)(Es + 1024);  // 1024 ints
    #pragma unroll
    for (int mi = 0; mi < 4; mi++) {
        redD[((ty << 2) + mi) * 16 + tx] = best[mi];
        redI[((ty << 2) + mi) * 16 + tx] = bidx[mi];
    }
    __syncthreads();
    if (tid < 64) {
        float bd = CUDART_INF_F; int bi = 0x7fffffff;
        #pragma unroll
        for (int t = 0; t < 16; t++) {
            float d  = redD[tid * 16 + t];
            int   ii = redI[tid * 16 + t];
            if (d < bd || (d == bd && ii < bi)) { bd = d; bi = ii; }
        }
        int row = row0 + tid;
        g_idx[row]   = bi;
        indOutF[row] = (float)bi;
        atomicAdd(&g_counts[bi], 1);
    }
}

// ============================================================
// Kernel 2: gather codes, straight-through output, diff partial sums.
// ============================================================
__global__ void __launch_bounds__(256) gather_kernel(
    const float* __restrict__ input, float* __restrict__ outQ)
{
    __shared__ double sred[256];
    int gid = blockIdx.x * 256 + threadIdx.x;  // float4 index
    int n  = gid >> 6;
    int d4 = gid & 63;
    int ind = g_idx[n];

    float4 e = *(const float4*)(g_embedT + (size_t)ind * DIM + (d4 << 2));
    float4 x = ((const float4*)input)[gid];

    float dx0 = __fsub_rn(e.x, x.x);
    float dx1 = __fsub_rn(e.y, x.y);
    float dx2 = __fsub_rn(e.z, x.z);
    float dx3 = __fsub_rn(e.w, x.w);

    float4 q;
    q.x = __fadd_rn(x.x, dx0);
    q.y = __fadd_rn(x.y, dx1);
    q.z = __fadd_rn(x.z, dx2);
    q.w = __fadd_rn(x.w, dx3);
    ((float4*)outQ)[gid] = q;

    double s = (double)__fmul_rn(dx0, dx0) + (double)__fmul_rn(dx1, dx1)
             + (double)__fmul_rn(dx2, dx2) + (double)__fmul_rn(dx3, dx3);

    sred[threadIdx.x] = s;
    __syncthreads();
    for (int o = 128; o > 0; o >>= 1) {
        if (threadIdx.x < o) sred[threadIdx.x] += sred[threadIdx.x + o];
        __syncthreads();
    }
    if (threadIdx.x == 0) g_partials[blockIdx.x] = sred[0];
}

// ============================================================
// Kernel 3: finalize diff (deterministic double sum) + perplexity.
// ============================================================
__global__ void __launch_bounds__(256) finalize_kernel(
    float* __restrict__ outDiff, float* __restrict__ outPerp)
{
    __shared__ double sred[256];
    int tid = threadIdx.x;

    double s = 0.0;
    for (int i = tid; i < GATHER_BLOCKS; i += 256) s += g_partials[i];
    sred[tid] = s;
    __syncthreads();
    for (int o = 128; o > 0; o >>= 1) {
        if (tid < o) sred[tid] += sred[tid + o];
        __syncthreads();
    }
    if (tid == 0) *outDiff = (float)(sred[0] / (double)QELEMS);
    __syncthreads();

    double ps = 0.0;
    for (int j = tid; j < NEMB; j += 256) {
        float p  = (float)g_counts[j] * (1.0f / 65536.0f);   // exact /2^16
        float cl = fmaxf(p, 1e-7f);
        ps += (double)__fmul_rn(p, logf(cl));                 // 0*log(clip)=0 ok
    }
    sred[tid] = ps;
    __syncthreads();
    for (int o = 128; o > 0; o >>= 1) {
        if (tid < o) sred[tid] += sred[tid + o];
        __syncthreads();
    }
    if (tid == 0) *outPerp = expf((float)(-sred[0]));
}

// ============================================================
// Output layout (float32, reference return order):
//   [0, 16777216)                quantize_st
//   [16777216]                   diff
//   [16777217, 16777217+65536)   embed_ind (as float)
//   [16842753]                   perplexity
// ============================================================
extern "C" void kernel_launch(void* const* d_in, const int* in_sizes, int n_in,
                              void* d_out, int out_size) {
    const float* input = (const float*)d_in[0];
    const float* embed = (const float*)d_in[1];
    float* out     = (float*)d_out;
    float* outQ    = out;
    float* outDiff = out + QELEMS;
    float* outInd  = out + QELEMS + 1;
    float* outPerp = out + QELEMS + 1 + NROWS;

    cudaFuncSetAttribute(dist_argmin_kernel,
                         cudaFuncAttributeMaxDynamicSharedMemorySize,
                         SMEM_MAIN_BYTES);

    prep_kernel<<<8, 256>>>(embed);
    dist_argmin_kernel<<<NROWS / 64, 256, SMEM_MAIN_BYTES>>>(input, embed, outInd);
    gather_kernel<<<GATHER_BLOCKS, 256>>>(input, outQ);
    finalize_kernel<<<1, 256>>>(outDiff, outPerp);
}